// round 14
// baseline (speedup 1.0000x reference)
#include <cuda_runtime.h>
#include <cuda_fp16.h>
#include <cstdint>

// ---------------- problem constants ----------------
#define NV    6000
#define RR    5
#define AA    8
#define FF    128
#define KK    2
#define OO    128
#define RA    40
#define NROT  8
#define NP    55                  // spectral p-rows incl. u (8 comps*5 + 3 u*5)
#define KDIMA 7040                // NP*128 A' columns
#define NGRP  11                  // column groups, each 256 cols, K=640
#define NJ2   (NGRP*256)          // 2816 spectral output cols
#define KG    640                 // uniform per-group K
#define NTILE (2*NGRP*47)         // 1034 GEMM tiles
#define NPERS 296                 // persistent CTAs (148 SM x 2)
#define NSPT  10                  // stages per tile (KG/BK)

// ---------------- GEMM tiling ----------------
#define BM    128
#define BN    128
#define BK    64
#define ASTB  144
#define A_BYTES (BM*ASTB)
#define B_BYTES (BN*ASTB)
#define STG_BYTES (A_BYTES + B_BYTES)
#define NSTG  3
#define DYNSMEM (NSTG*STG_BYTES)  // 110592 -> 2 CTAs/SM

// gatherA dynamic smem (halves): M 64x56, 2x sig 48x136, 2x out 64x136
#define GA_M    0
#define GA_SIG0 3584
#define GA_SIG1 (3584+6528)
#define GA_OUT0 (3584+2*6528)
#define GA_OUT1 (3584+2*6528+8704)
#define GA_SMEM ((3584+2*6528+2*8704)*2)   // 66560 bytes

// ---------------- scratch ----------------
__device__ __half g_ms16[(size_t)NV * FF];     // fp16 mesh signal
__device__ __half g_A [(size_t)NV * KDIMA];    // spectral A' (+u cols)
__device__ __half g_B2[(size_t)NJ2 * KG];      // Karatsuba B
__device__ float  g_S [(size_t)NV * NJ2];      // spectral GEMM result
__device__ __half g_Mh[64 * 48];               // padded fold matrix (fp16)

__device__ __constant__ int c_aoff[NGRP] =
    {0, 4480, 5120, 640, 1280, 5760, 1920, 2560, 6400, 3200, 3840};

// ---------------- PTX helpers ----------------
__device__ __forceinline__ uint32_t smem_u32(const void* p) {
    uint32_t a;
    asm("{ .reg .u64 t; cvta.to.shared.u64 t, %1; cvt.u32.u64 %0, t; }"
        : "=r"(a) : "l"(p));
    return a;
}
__device__ __forceinline__ void cpasync16(uint32_t saddr, const void* g, int srcsz) {
    asm volatile("cp.async.cg.shared.global [%0], [%1], 16, %2;"
                 :: "r"(saddr), "l"(g), "r"(srcsz) : "memory");
}
#define CP_COMMIT() asm volatile("cp.async.commit_group;" ::: "memory")
#define CP_WAIT1()  asm volatile("cp.async.wait_group 1;" ::: "memory")

__device__ __forceinline__ void ldsm_x4(uint32_t* r, uint32_t addr) {
    asm volatile("ldmatrix.sync.aligned.m8n8.x4.shared.b16 {%0,%1,%2,%3}, [%4];"
                 : "=r"(r[0]), "=r"(r[1]), "=r"(r[2]), "=r"(r[3]) : "r"(addr));
}
__device__ __forceinline__ void ldsm_x4_t(uint32_t* r, uint32_t addr) {
    asm volatile("ldmatrix.sync.aligned.m8n8.x4.trans.shared.b16 {%0,%1,%2,%3}, [%4];"
                 : "=r"(r[0]), "=r"(r[1]), "=r"(r[2]), "=r"(r[3]) : "r"(addr));
}
__device__ __forceinline__ void mma_f16(float* d, const uint32_t* a, const uint32_t* b) {
    asm volatile(
        "mma.sync.aligned.m16n8k16.row.col.f32.f16.f16.f32 "
        "{%0,%1,%2,%3}, {%4,%5,%6,%7}, {%8,%9}, {%0,%1,%2,%3};"
        : "+f"(d[0]), "+f"(d[1]), "+f"(d[2]), "+f"(d[3])
        : "r"(a[0]), "r"(a[1]), "r"(a[2]), "r"(a[3]), "r"(b[0]), "r"(b[1]));
}

// ---------------------------------------------------------------------------
// Kernel 1 (merged prep): blocks [0,256) buildB one-pass; [256,1006) conv_ms;
//                          [1006,1030) make_M.  128 threads.
// ---------------------------------------------------------------------------
__global__ void __launch_bounds__(128)
prep(const float* __restrict__ ms, const float* __restrict__ W,
     const float* __restrict__ interp)
{
    const int bid = blockIdx.x;
    const int tid = threadIdx.x;

    if (bid < 256) {
        // ---- buildB: one pass over W per (k,o) ----
        const int k = bid >> 7;
        const int o = bid & 127;
        const int f = tid;
        const int ko = k * OO + o;

        float w[RR][AA];
        #pragma unroll
        for (int r = 0; r < RR; r++)
            #pragma unroll
            for (int b = 0; b < AA; b++)
                w[r][b] = __ldg(&W[((((size_t)(r * AA + b)) * KK + k) * OO + o) * FF + f]);

        #pragma unroll
        for (int r = 0; r < RR; r++) {
            float s0 = 0.f, s4 = 0.f;
            #pragma unroll
            for (int b = 0; b < AA; b++) {
                s0 += w[r][b];
                s4 += ((b & 1) ? -w[r][b] : w[r][b]);
            }
            g_B2[(size_t)(0 * 256 + ko) * KG + r * FF + f] = __float2half_rn(0.125f * s0);
            g_B2[(size_t)(1 * 256 + ko) * KG + r * FF + f] = __float2half_rn(0.125f * s4);
        }
        #pragma unroll
        for (int om = 1; om <= 3; om++) {
            const int base = 2 + 3 * (om - 1);
            #pragma unroll
            for (int r = 0; r < RR; r++) {
                float sr = 0.f, si = 0.f;
                #pragma unroll
                for (int b = 0; b < AA; b++) {
                    const float x = 0.25f * (float)(om * b);
                    sr = fmaf(cospif(x), w[r][b], sr);
                    si = fmaf(-sinpif(x), w[r][b], si);
                }
                const float whr = 0.25f * sr, whi = 0.25f * si;
                g_B2[(size_t)((base    ) * 256 + ko) * KG + r * FF + f] = __float2half_rn(whi);
                g_B2[(size_t)((base + 1) * 256 + ko) * KG + r * FF + f] = __float2half_rn(whr - whi);
                g_B2[(size_t)((base + 2) * 256 + ko) * KG + r * FF + f] = __float2half_rn(whr + whi);
            }
        }
    } else if (bid < 1006) {
        // ---- conv_ms: fp32 -> fp16 signal (4 float2 per thread) ----
        const int base = (bid - 256) * 512 + tid * 4;
        #pragma unroll
        for (int j = 0; j < 4; j++) {
            const int i = base + j;
            if (i < NV * FF / 2) {
                const float2 v = __ldg((const float2*)ms + i);
                *((__half2*)g_ms16 + i) = __floats2half2_rn(v.x, v.y);
            }
        }
    } else {
        // ---- make_M: padded fold matrix ----
        const int e = (bid - 1006) * 128 + tid;     // 0..3071
        const int p = e / 48, q = e % 48;
        float acc = 0.f;
        if (p < NP && q < RA) {
            const int r = p % RR;
            #pragma unroll
            for (int b = 0; b < AA; b++) {
                float coef;
                if (p < RA) {
                    const int comp = p / RR;
                    if (comp == 0)      coef = 1.f;
                    else if (comp == 7) coef = (b & 1) ? -1.f : 1.f;
                    else {
                        const int m = (comp + 1) >> 1;
                        const float x = 0.25f * (float)(m * b);
                        coef = (comp & 1) ? cospif(x) : -sinpif(x);
                    }
                } else {
                    const int om = (p - RA) / RR + 1;
                    const float x = 0.25f * (float)(om * b);
                    coef = cospif(x) - sinpif(x);
                }
                acc += coef * interp[r * (AA * RA) + b * RA + q];
            }
        }
        g_Mh[p * 48 + q] = __float2half_rn(acc);
    }
}

// ---------------------------------------------------------------------------
// Kernel 2: gatherA — 2 vertices per block (amortize M load, double MLP).
// ---------------------------------------------------------------------------
__global__ void __launch_bounds__(256)
gatherA(const float* __restrict__ bary)
{
    extern __shared__ __half sm[];
    __half* s_M = sm + GA_M;                  // [64][56]

    const int n0   = blockIdx.x * 2;
    const int tid  = threadIdx.x;
    const int wid  = tid >> 5;
    const int lane = tid & 31;

    for (int i = tid; i < 64 * 56; i += 256) {
        const int r = i / 56, c = i % 56;
        s_M[r * 56 + c] = (c < 48) ? g_Mh[r * 48 + c] : __float2half_rn(0.f);
    }
    // zero sig pad rows 40..47 (both v)
    for (int i = tid; i < 2 * 8 * 68; i += 256) {
        const int v = i / (8 * 68), rr = (i % (8 * 68)) / 68, cc = i % 68;
        __half* s_sig = sm + (v ? GA_SIG1 : GA_SIG0);
        *((uint32_t*)(s_sig + (40 + rr) * 136) + cc) = 0u;
    }

    // gather: 80 warp-rows (2 vertices x 40 q) over 8 warps x 10 its
    #pragma unroll
    for (int it = 0; it < 10; it++) {
        const int qa  = wid + 8 * it;         // 0..79
        const int v   = qa / RA;
        const int q   = qa % RA;
        const int row = (n0 + v) * RA + q;
        __half* s_sig = sm + (v ? GA_SIG1 : GA_SIG0);

        float bv = (lane < 6) ? bary[(size_t)row * 6 + lane] : 0.f;
        const int   i0 = (int)__shfl_sync(0xffffffffu, bv, 0);
        const float w0 =      __shfl_sync(0xffffffffu, bv, 1);
        const int   i1 = (int)__shfl_sync(0xffffffffu, bv, 2);
        const float w1 =      __shfl_sync(0xffffffffu, bv, 3);
        const int   i2 = (int)__shfl_sync(0xffffffffu, bv, 4);
        const float w2 =      __shfl_sync(0xffffffffu, bv, 5);

        const uint2 pa = __ldg((const uint2*)(g_ms16 + (size_t)i0 * FF) + lane);
        const uint2 pb = __ldg((const uint2*)(g_ms16 + (size_t)i1 * FF) + lane);
        const uint2 pc = __ldg((const uint2*)(g_ms16 + (size_t)i2 * FF) + lane);
        const float2 a01 = __half22float2(*(const __half2*)&pa.x);
        const float2 a23 = __half22float2(*(const __half2*)&pa.y);
        const float2 b01 = __half22float2(*(const __half2*)&pb.x);
        const float2 b23 = __half22float2(*(const __half2*)&pb.y);
        const float2 c01 = __half22float2(*(const __half2*)&pc.x);
        const float2 c23 = __half22float2(*(const __half2*)&pc.y);

        const float v0 = w0 * a01.x + w1 * b01.x + w2 * c01.x;
        const float v1 = w0 * a01.y + w1 * b01.y + w2 * c01.y;
        const float v2 = w0 * a23.x + w1 * b23.x + w2 * c23.x;
        const float v3 = w0 * a23.y + w1 * b23.y + w2 * c23.y;
        *(__half2*)(s_sig + q * 136 + lane * 4)     = __floats2half2_rn(v0, v1);
        *(__half2*)(s_sig + q * 136 + lane * 4 + 2) = __floats2half2_rn(v2, v3);
    }
    __syncthreads();

    const uint32_t sMb = smem_u32(sm + GA_M);
    const int grp = lane >> 3;
    const int wit = lane & 7;
    const int nc  = wid;

    #pragma unroll
    for (int v = 0; v < 2; v++) {
        const uint32_t sSb = smem_u32(sm + (v ? GA_SIG1 : GA_SIG0));
        __half* s_out = sm + (v ? GA_OUT1 : GA_OUT0);

        uint32_t bfr[3][4];
        #pragma unroll
        for (int ks = 0; ks < 3; ks++)
            ldsm_x4_t(bfr[ks], sSb + (uint32_t)((ks * 16 + (grp & 1) * 8 + wit) * 272
                                                + (grp >> 1) * 16 + nc * 32));
        #pragma unroll
        for (int mt = 0; mt < 4; mt++) {
            float acc[2][4] = {{0.f,0.f,0.f,0.f},{0.f,0.f,0.f,0.f}};
            #pragma unroll
            for (int ks = 0; ks < 3; ks++) {
                uint32_t a[4];
                ldsm_x4(a, sMb + (uint32_t)((mt * 16 + (grp & 1) * 8 + wit) * 112
                                            + (grp >> 1) * 16 + ks * 32));
                mma_f16(acc[0], a, &bfr[ks][0]);
                mma_f16(acc[1], a, &bfr[ks][2]);
            }
            const int p  = mt * 16 + (lane >> 2);
            const int fb = nc * 16 + 2 * (lane & 3);
            *(__half2*)(s_out + p * 136 + fb)           = __floats2half2_rn(acc[0][0], acc[0][1]);
            *(__half2*)(s_out + (p + 8) * 136 + fb)     = __floats2half2_rn(acc[0][2], acc[0][3]);
            *(__half2*)(s_out + p * 136 + fb + 8)       = __floats2half2_rn(acc[1][0], acc[1][1]);
            *(__half2*)(s_out + (p + 8) * 136 + fb + 8) = __floats2half2_rn(acc[1][2], acc[1][3]);
        }
    }
    __syncthreads();

    for (int i = tid; i < 2 * NP * 16; i += 256) {
        const int v = i / (NP * 16);
        const int e = i % (NP * 16);
        const int r = e >> 4, c = e & 15;
        const __half* s_out = sm + (v ? GA_OUT1 : GA_OUT0);
        uint4 val = *(const uint4*)(s_out + r * 136 + c * 8);
        *(uint4*)(g_A + (size_t)(n0 + v) * KDIMA + r * FF + c * 8) = val;
    }
}

// ---------------------------------------------------------------------------
// Kernel 3: persistent GEMM with CONTINUOUS cross-tile cp.async pipeline.
//   Global stage gs: tile = gs/10, k-stage = gs%10, buffer = gs%3.
//   Pipeline never drains between tiles.
// ---------------------------------------------------------------------------
__global__ void __launch_bounds__(256, 2)
gemm_mma()
{
    extern __shared__ char smem[];
    const uint32_t sbase = smem_u32(smem);

    const int tid = threadIdx.x;
    const int lid = tid & 31;
    const int wid = tid >> 5;
    const int wm  = wid >> 2;
    const int wn  = wid & 3;

    const int grp = lid >> 3;
    const int wit = lid & 7;
    const uint32_t aoffs = (uint32_t)((wm * 64 + (grp & 1) * 8 + wit) * ASTB
                                      + (grp >> 1) * 16);
    const uint32_t boffs = (uint32_t)A_BYTES
                         + (uint32_t)((wn * 32 + (grp >> 1) * 8 + wit) * ASTB
                                      + (grp & 1) * 16);

    const int ntl   = (NTILE - blockIdx.x + NPERS - 1) / NPERS;  // tiles for this CTA
    const int NSall = ntl * NSPT;

    auto issue_stage = [&](int g) {
        if (g >= NSall) { CP_COMMIT(); return; }   // ghost commit keeps counts aligned
        const int ti = g / NSPT;
        const int s  = g % NSPT;
        const int T  = blockIdx.x + ti * NPERS;
        const int cg = T % (2 * NGRP);
        const int gr = cg >> 1;
        const int m0 = (T / (2 * NGRP)) * BM;
        const int n0 = gr * 256 + (cg & 1) * 128;
        const int aoff = c_aoff[gr];
        const int kk0 = s * BK;
        const uint32_t sb = sbase + (uint32_t)(g % NSTG) * STG_BYTES;
        #pragma unroll
        for (int i = 0; i < 4; i++) {
            const int id  = tid + i * 256;
            const int r   = id >> 3;
            const int c16 = id & 7;
            const int gm  = m0 + r;
            const bool v  = gm < NV;
            const __half* gp = g_A + (size_t)(v ? gm : 0) * KDIMA + aoff + kk0 + c16 * 8;
            cpasync16(sb + r * ASTB + c16 * 16, gp, v ? 16 : 0);
        }
        #pragma unroll
        for (int i = 0; i < 4; i++) {
            const int id  = tid + i * 256;
            const int r   = id >> 3;
            const int c16 = id & 7;
            const __half* gp = g_B2 + (size_t)(n0 + r) * KG + kk0 + c16 * 8;
            cpasync16(sb + A_BYTES + r * ASTB + c16 * 16, gp, 16);
        }
        CP_COMMIT();
    };

    issue_stage(0);
    issue_stage(1);

    float acc[4][4][4];
    #pragma unroll
    for (int mt = 0; mt < 4; mt++)
        #pragma unroll
        for (int nt = 0; nt < 4; nt++)
            #pragma unroll
            for (int i = 0; i < 4; i++) acc[mt][nt][i] = 0.f;

    for (int gs = 0; gs < NSall; gs++) {
        CP_WAIT1();
        __syncthreads();
        issue_stage(gs + 2);

        const uint32_t sb = sbase + (uint32_t)(gs % NSTG) * STG_BYTES;
        #pragma unroll
        for (int ks = 0; ks < 4; ks++) {
            uint32_t a[4][4], b[2][4];
            #pragma unroll
            for (int mt = 0; mt < 4; mt++)
                ldsm_x4(a[mt], sb + aoffs + mt * (16 * ASTB) + ks * 32);
            #pragma unroll
            for (int np = 0; np < 2; np++)
                ldsm_x4(b[np], sb + boffs + np * (16 * ASTB) + ks * 32);
            #pragma unroll
            for (int mt = 0; mt < 4; mt++) {
                #pragma unroll
                for (int np = 0; np < 2; np++) {
                    mma_f16(acc[mt][2 * np],     a[mt], &b[np][0]);
                    mma_f16(acc[mt][2 * np + 1], a[mt], &b[np][2]);
                }
            }
        }

        if (gs % NSPT == NSPT - 1) {
            // end of tile: store accumulators, reset
            const int T  = blockIdx.x + (gs / NSPT) * NPERS;
            const int cg = T % (2 * NGRP);
            const int m0 = (T / (2 * NGRP)) * BM;
            const int n0 = (cg >> 1) * 256 + (cg & 1) * 128;
            const int q4 = lid >> 2;
            const int r4 = lid & 3;
            #pragma unroll
            for (int mt = 0; mt < 4; mt++) {
                const int r  = wm * 64 + mt * 16 + q4;
                const int gm = m0 + r;
                #pragma unroll
                for (int nt = 0; nt < 4; nt++) {
                    const int c = wn * 32 + nt * 8 + 2 * r4;
                    if (gm < NV)
                        *(float2*)&g_S[(size_t)gm * NJ2 + n0 + c] =
                            make_float2(acc[mt][nt][0], acc[mt][nt][1]);
                    if (gm + 8 < NV)
                        *(float2*)&g_S[(size_t)(gm + 8) * NJ2 + n0 + c] =
                            make_float2(acc[mt][nt][2], acc[mt][nt][3]);
                    acc[mt][nt][0] = acc[mt][nt][1] = 0.f;
                    acc[mt][nt][2] = acc[mt][nt][3] = 0.f;
                }
            }
        }
    }
}

// ---------------------------------------------------------------------------
// Kernel 4: Karatsuba combine + inverse FFT + bias + relu + k-sum
// ---------------------------------------------------------------------------
__global__ void epilogue(const float* __restrict__ bias, float* __restrict__ out)
{
    const int n = blockIdx.x;
    const int o = threadIdx.x;
    const float* S = g_S + (size_t)n * NJ2;

    float C0[2], C4[2], CR[3][2], CI[3][2];
    #pragma unroll
    for (int k = 0; k < 2; k++) {
        C0[k] = S[k * OO + o];
        C4[k] = S[256 + k * OO + o];
        #pragma unroll
        for (int om = 1; om <= 3; om++) {
            const int base = (2 + 3 * (om - 1)) * 256 + k * OO + o;
            const float m1 = S[base], m2 = S[base + 256], m3 = S[base + 512];
            CR[om - 1][k] = m1 + m2;
            CI[om - 1][k] = m1 - m3;
        }
    }

    const float ct[8] = {1.f, 0.70710678f, 0.f, -0.70710678f,
                         -1.f, -0.70710678f, 0.f, 0.70710678f};
    const float st[8] = {0.f, 0.70710678f, 1.f, 0.70710678f,
                         0.f, -0.70710678f, -1.f, -0.70710678f};
    const float b0 = 40.f * __ldg(&bias[o]);
    const float b1 = 40.f * __ldg(&bias[OO + o]);

    #pragma unroll
    for (int rot = 0; rot < 8; rot++) {
        const float sgn = (rot & 1) ? -1.f : 1.f;
        float s0 = C0[0] + sgn * C4[0];
        float s1 = C0[1] + sgn * C4[1];
        #pragma unroll
        for (int om = 1; om <= 3; om++) {
            const int ph = (om * rot) & 7;
            s0 += CR[om - 1][0] * ct[ph] - CI[om - 1][0] * st[ph];
            s1 += CR[om - 1][1] * ct[ph] - CI[om - 1][1] * st[ph];
        }
        out[(size_t)n * (NROT * OO) + rot * OO + o] =
            fmaxf(s0 + b0, 0.f) + fmaxf(s1 + b1, 0.f);
    }
}

// ---------------------------------------------------------------------------
extern "C" void kernel_launch(void* const* d_in, const int* in_sizes, int n_in,
                              void* d_out, int out_size)
{
    const float *ms = nullptr, *bary = nullptr, *W = nullptr,
                *bias = nullptr, *interp = nullptr;
    for (int i = 0; i < n_in; i++) {
        switch (in_sizes[i]) {
            case NV * FF:             ms     = (const float*)d_in[i]; break;
            case NV * RA * 3 * 2:     bary   = (const float*)d_in[i]; break;
            case RA * KK * OO * FF:   W      = (const float*)d_in[i]; break;
            case KK * OO:             bias   = (const float*)d_in[i]; break;
            case RA * RA:             interp = (const float*)d_in[i]; break;
            default: break;
        }
    }
    float* out = (float*)d_out;

    prep<<<1030, 128>>>(ms, W, interp);

    cudaFuncSetAttribute(gatherA, cudaFuncAttributeMaxDynamicSharedMemorySize, GA_SMEM);
    gatherA<<<NV / 2, 256, GA_SMEM>>>(bary);

    cudaFuncSetAttribute(gemm_mma, cudaFuncAttributeMaxDynamicSharedMemorySize, DYNSMEM);
    gemm_mma<<<NPERS, 256, DYNSMEM>>>();

    epilogue<<<NV, OO>>>(bias, out);
}

// round 15
// speedup vs baseline: 1.0646x; 1.0646x over previous
#include <cuda_runtime.h>
#include <cuda_fp16.h>
#include <cstdint>

// ---------------- problem constants ----------------
#define NV    6000
#define RR    5
#define AA    8
#define FF    128
#define KK    2
#define OO    128
#define RA    40
#define NROT  8
#define NP    55                  // spectral p-rows incl. u (8 comps*5 + 3 u*5)
#define KDIMA 7040                // NP*128 A' columns
#define NGRP  11                  // column groups, each 256 cols, K=640
#define NJ2   (NGRP*256)          // 2816 spectral output cols
#define KG    640                 // uniform per-group K

// ---------------- GEMM tiling ----------------
#define BM    128
#define BN    128
#define BK    64
#define ASTB  144
#define A_BYTES (BM*ASTB)
#define B_BYTES (BN*ASTB)
#define STG_BYTES (A_BYTES + B_BYTES)
#define NSTG  3
#define DYNSMEM (NSTG*STG_BYTES)  // 110592 -> 2 CTAs/SM

// ---------------- scratch ----------------
__device__ __half g_A [(size_t)NV * KDIMA];    // spectral A' (+u cols)
__device__ __half g_B2[(size_t)NJ2 * KG];      // Karatsuba B
__device__ float  g_S [(size_t)NV * NJ2];      // spectral GEMM result
__device__ __half g_Mh[64 * 48];               // padded fold matrix (fp16)

__device__ __constant__ int c_aoff[NGRP] =
    {0, 4480, 5120, 640, 1280, 5760, 1920, 2560, 6400, 3200, 3840};

// ---------------- PTX helpers ----------------
__device__ __forceinline__ uint32_t smem_u32(const void* p) {
    uint32_t a;
    asm("{ .reg .u64 t; cvta.to.shared.u64 t, %1; cvt.u32.u64 %0, t; }"
        : "=r"(a) : "l"(p));
    return a;
}
__device__ __forceinline__ void cpasync16(uint32_t saddr, const void* g, int srcsz) {
    asm volatile("cp.async.cg.shared.global [%0], [%1], 16, %2;"
                 :: "r"(saddr), "l"(g), "r"(srcsz) : "memory");
}
#define CP_COMMIT() asm volatile("cp.async.commit_group;" ::: "memory")
#define CP_WAIT1()  asm volatile("cp.async.wait_group 1;" ::: "memory")

__device__ __forceinline__ void ldsm_x4(uint32_t* r, uint32_t addr) {
    asm volatile("ldmatrix.sync.aligned.m8n8.x4.shared.b16 {%0,%1,%2,%3}, [%4];"
                 : "=r"(r[0]), "=r"(r[1]), "=r"(r[2]), "=r"(r[3]) : "r"(addr));
}
__device__ __forceinline__ void ldsm_x4_t(uint32_t* r, uint32_t addr) {
    asm volatile("ldmatrix.sync.aligned.m8n8.x4.trans.shared.b16 {%0,%1,%2,%3}, [%4];"
                 : "=r"(r[0]), "=r"(r[1]), "=r"(r[2]), "=r"(r[3]) : "r"(addr));
}
__device__ __forceinline__ void mma_f16(float* d, const uint32_t* a, const uint32_t* b) {
    asm volatile(
        "mma.sync.aligned.m16n8k16.row.col.f32.f16.f16.f32 "
        "{%0,%1,%2,%3}, {%4,%5,%6,%7}, {%8,%9}, {%0,%1,%2,%3};"
        : "+f"(d[0]), "+f"(d[1]), "+f"(d[2]), "+f"(d[3])
        : "r"(a[0]), "r"(a[1]), "r"(a[2]), "r"(a[3]), "r"(b[0]), "r"(b[1]));
}

// ---------------------------------------------------------------------------
// Kernel 1 (merged prep): blocks [0,256) buildB one-pass; [256,280) make_M.
// ---------------------------------------------------------------------------
__global__ void __launch_bounds__(128)
prep(const float* __restrict__ W, const float* __restrict__ interp)
{
    const int bid = blockIdx.x;
    const int tid = threadIdx.x;

    if (bid < 256) {
        // ---- buildB: one pass over W per (k,o), emit all 11 spectral rows ----
        const int k = bid >> 7;
        const int o = bid & 127;
        const int f = tid;
        const int ko = k * OO + o;

        float w[RR][AA];
        #pragma unroll
        for (int r = 0; r < RR; r++)
            #pragma unroll
            for (int b = 0; b < AA; b++)
                w[r][b] = __ldg(&W[((((size_t)(r * AA + b)) * KK + k) * OO + o) * FF + f]);

        #pragma unroll
        for (int r = 0; r < RR; r++) {
            float s0 = 0.f, s4 = 0.f;
            #pragma unroll
            for (int b = 0; b < AA; b++) {
                s0 += w[r][b];
                s4 += ((b & 1) ? -w[r][b] : w[r][b]);
            }
            g_B2[(size_t)(0 * 256 + ko) * KG + r * FF + f] = __float2half_rn(0.125f * s0);
            g_B2[(size_t)(1 * 256 + ko) * KG + r * FF + f] = __float2half_rn(0.125f * s4);
        }
        #pragma unroll
        for (int om = 1; om <= 3; om++) {
            const int base = 2 + 3 * (om - 1);
            #pragma unroll
            for (int r = 0; r < RR; r++) {
                float sr = 0.f, si = 0.f;
                #pragma unroll
                for (int b = 0; b < AA; b++) {
                    const float x = 0.25f * (float)(om * b);
                    sr = fmaf(cospif(x), w[r][b], sr);
                    si = fmaf(-sinpif(x), w[r][b], si);
                }
                const float whr = 0.25f * sr, whi = 0.25f * si;
                g_B2[(size_t)((base    ) * 256 + ko) * KG + r * FF + f] = __float2half_rn(whi);
                g_B2[(size_t)((base + 1) * 256 + ko) * KG + r * FF + f] = __float2half_rn(whr - whi);
                g_B2[(size_t)((base + 2) * 256 + ko) * KG + r * FF + f] = __float2half_rn(whr + whi);
            }
        }
    } else {
        // ---- make_M: padded fold matrix (64x48) ----
        const int e = (bid - 256) * 128 + tid;     // 0..3071
        const int p = e / 48, q = e % 48;
        float acc = 0.f;
        if (p < NP && q < RA) {
            const int r = p % RR;
            #pragma unroll
            for (int b = 0; b < AA; b++) {
                float coef;
                if (p < RA) {
                    const int comp = p / RR;
                    if (comp == 0)      coef = 1.f;
                    else if (comp == 7) coef = (b & 1) ? -1.f : 1.f;
                    else {
                        const int m = (comp + 1) >> 1;
                        const float x = 0.25f * (float)(m * b);
                        coef = (comp & 1) ? cospif(x) : -sinpif(x);
                    }
                } else {                       // u-rows: cos - sin
                    const int om = (p - RA) / RR + 1;
                    const float x = 0.25f * (float)(om * b);
                    coef = cospif(x) - sinpif(x);
                }
                acc += coef * interp[r * (AA * RA) + b * RA + q];
            }
        }
        g_Mh[p * 48 + q] = __float2half_rn(acc);
    }
}

// ---------------------------------------------------------------------------
// Kernel 2: gather (fp32) + barycentric -> smem; HMMA fold A' = M*sig.
//           (R12 known-good form)
// ---------------------------------------------------------------------------
__global__ void __launch_bounds__(256)
gatherA(const float* __restrict__ ms, const float* __restrict__ bary)
{
    __shared__ __half s_M  [64][56];   // stride 112B -> conflict-free ldsm
    __shared__ __half s_sig[48][136];  // stride 272B -> conflict-free trans-ldsm
    __shared__ __half s_out[64][136];  // fold result staging

    const int n    = blockIdx.x;
    const int tid  = threadIdx.x;
    const int wid  = tid >> 5;
    const int lane = tid & 31;

    for (int i = tid; i < 64 * 56; i += 256) {
        const int r = i / 56, c = i % 56;
        s_M[r][c] = (c < 48) ? g_Mh[r * 48 + c] : __float2half_rn(0.f);
    }
    for (int i = tid; i < 8 * 68; i += 256)
        *((uint32_t*)&s_sig[40 + i / 68][0] + (i % 68)) = 0u;

    #pragma unroll
    for (int it = 0; it < 5; it++) {
        const int q   = wid + 8 * it;
        const int row = n * RA + q;
        float bv = (lane < 6) ? bary[(size_t)row * 6 + lane] : 0.f;
        const int   i0 = (int)__shfl_sync(0xffffffffu, bv, 0);
        const float w0 =      __shfl_sync(0xffffffffu, bv, 1);
        const int   i1 = (int)__shfl_sync(0xffffffffu, bv, 2);
        const float w1 =      __shfl_sync(0xffffffffu, bv, 3);
        const int   i2 = (int)__shfl_sync(0xffffffffu, bv, 4);
        const float w2 =      __shfl_sync(0xffffffffu, bv, 5);

        const float4 a = __ldg((const float4*)(ms + (size_t)i0 * FF) + lane);
        const float4 b = __ldg((const float4*)(ms + (size_t)i1 * FF) + lane);
        const float4 c = __ldg((const float4*)(ms + (size_t)i2 * FF) + lane);
        const float v0 = w0 * a.x + w1 * b.x + w2 * c.x;
        const float v1 = w0 * a.y + w1 * b.y + w2 * c.y;
        const float v2 = w0 * a.z + w1 * b.z + w2 * c.z;
        const float v3 = w0 * a.w + w1 * b.w + w2 * c.w;
        *(__half2*)&s_sig[q][lane * 4]     = __floats2half2_rn(v0, v1);
        *(__half2*)&s_sig[q][lane * 4 + 2] = __floats2half2_rn(v2, v3);
    }
    __syncthreads();

    const uint32_t sMb = smem_u32(&s_M[0][0]);
    const uint32_t sSb = smem_u32(&s_sig[0][0]);
    const int grp = lane >> 3;
    const int wit = lane & 7;
    const int nc  = wid;

    uint32_t bfr[3][4];
    #pragma unroll
    for (int ks = 0; ks < 3; ks++)
        ldsm_x4_t(bfr[ks], sSb + (uint32_t)((ks * 16 + (grp & 1) * 8 + wit) * 272
                                            + (grp >> 1) * 16 + nc * 32));
    #pragma unroll
    for (int mt = 0; mt < 4; mt++) {
        float acc[2][4] = {{0.f,0.f,0.f,0.f},{0.f,0.f,0.f,0.f}};
        #pragma unroll
        for (int ks = 0; ks < 3; ks++) {
            uint32_t a[4];
            ldsm_x4(a, sMb + (uint32_t)((mt * 16 + (grp & 1) * 8 + wit) * 112
                                        + (grp >> 1) * 16 + ks * 32));
            mma_f16(acc[0], a, &bfr[ks][0]);
            mma_f16(acc[1], a, &bfr[ks][2]);
        }
        const int p  = mt * 16 + (lane >> 2);
        const int fb = nc * 16 + 2 * (lane & 3);
        *(__half2*)&s_out[p][fb]         = __floats2half2_rn(acc[0][0], acc[0][1]);
        *(__half2*)&s_out[p + 8][fb]     = __floats2half2_rn(acc[0][2], acc[0][3]);
        *(__half2*)&s_out[p][fb + 8]     = __floats2half2_rn(acc[1][0], acc[1][1]);
        *(__half2*)&s_out[p + 8][fb + 8] = __floats2half2_rn(acc[1][2], acc[1][3]);
    }
    __syncthreads();

    for (int i = tid; i < NP * 16; i += 256) {
        const int r = i >> 4, c = i & 15;
        uint4 v = *(const uint4*)&s_out[r][c * 8];
        *(uint4*)(g_A + (size_t)n * KDIMA + r * FF + c * 8) = v;
    }
}

// ---------------------------------------------------------------------------
// Kernel 3: uniform block-diagonal GEMM (R12 known-good).  grid (22, 47),
//   cg fastest -> A-slice L2 reuse.  2 CTAs/SM.
// ---------------------------------------------------------------------------
__global__ void __launch_bounds__(256, 2)
gemm_mma()
{
    extern __shared__ char smem[];
    const uint32_t sbase = smem_u32(smem);

    const int tid = threadIdx.x;
    const int lid = tid & 31;
    const int wid = tid >> 5;
    const int wm  = wid >> 2;
    const int wn  = wid & 3;
    const int cg  = blockIdx.x;
    const int m0  = blockIdx.y * BM;
    const int gr  = cg >> 1;
    const int n0  = gr * 256 + (cg & 1) * 128;
    const int aoff = c_aoff[gr];
    const int ns   = KG / BK;            // 10

    const int grp = lid >> 3;
    const int wit = lid & 7;
    const uint32_t aoffs = (uint32_t)((wm * 64 + (grp & 1) * 8 + wit) * ASTB
                                      + (grp >> 1) * 16);
    const uint32_t boffs = (uint32_t)A_BYTES
                         + (uint32_t)((wn * 32 + (grp >> 1) * 8 + wit) * ASTB
                                      + (grp & 1) * 16);

    float acc[4][4][4];
    #pragma unroll
    for (int mt = 0; mt < 4; mt++)
        #pragma unroll
        for (int nt = 0; nt < 4; nt++)
            #pragma unroll
            for (int i = 0; i < 4; i++) acc[mt][nt][i] = 0.f;

    auto issue_stage = [&](int sp) {
        const int kk0 = sp * BK;
        const uint32_t sb = sbase + (uint32_t)(sp % NSTG) * STG_BYTES;
        #pragma unroll
        for (int i = 0; i < 4; i++) {
            const int id  = tid + i * 256;
            const int r   = id >> 3;
            const int c16 = id & 7;
            const int gm  = m0 + r;
            const bool v  = gm < NV;
            const __half* gp = g_A + (size_t)(v ? gm : 0) * KDIMA + aoff + kk0 + c16 * 8;
            cpasync16(sb + r * ASTB + c16 * 16, gp, v ? 16 : 0);
        }
        #pragma unroll
        for (int i = 0; i < 4; i++) {
            const int id  = tid + i * 256;
            const int r   = id >> 3;
            const int c16 = id & 7;
            const __half* gp = g_B2 + (size_t)(n0 + r) * KG + kk0 + c16 * 8;
            cpasync16(sb + A_BYTES + r * ASTB + c16 * 16, gp, 16);
        }
        CP_COMMIT();
    };

    issue_stage(0);
    issue_stage(1);

    for (int s = 0; s < ns; s++) {
        CP_WAIT1();
        __syncthreads();
        if (s + 2 < ns) issue_stage(s + 2); else CP_COMMIT();

        const uint32_t sb = sbase + (uint32_t)(s % NSTG) * STG_BYTES;
        #pragma unroll
        for (int ks = 0; ks < 4; ks++) {
            uint32_t a[4][4], b[2][4];
            #pragma unroll
            for (int mt = 0; mt < 4; mt++)
                ldsm_x4(a[mt], sb + aoffs + mt * (16 * ASTB) + ks * 32);
            #pragma unroll
            for (int np = 0; np < 2; np++)
                ldsm_x4(b[np], sb + boffs + np * (16 * ASTB) + ks * 32);
            #pragma unroll
            for (int mt = 0; mt < 4; mt++) {
                #pragma unroll
                for (int np = 0; np < 2; np++) {
                    mma_f16(acc[mt][2 * np],     a[mt], &b[np][0]);
                    mma_f16(acc[mt][2 * np + 1], a[mt], &b[np][2]);
                }
            }
        }
    }

    const int q4 = lid >> 2;
    const int r4 = lid & 3;
    #pragma unroll
    for (int mt = 0; mt < 4; mt++) {
        const int r  = wm * 64 + mt * 16 + q4;
        const int gm = m0 + r;
        #pragma unroll
        for (int nt = 0; nt < 4; nt++) {
            const int c = wn * 32 + nt * 8 + 2 * r4;
            if (gm < NV)
                *(float2*)&g_S[(size_t)gm * NJ2 + n0 + c] =
                    make_float2(acc[mt][nt][0], acc[mt][nt][1]);
            if (gm + 8 < NV)
                *(float2*)&g_S[(size_t)(gm + 8) * NJ2 + n0 + c] =
                    make_float2(acc[mt][nt][2], acc[mt][nt][3]);
        }
    }
}

// ---------------------------------------------------------------------------
// Kernel 4: vectorized Karatsuba combine + iFFT + bias + relu + k-sum.
//   256 threads, 8 vertices per block, thread owns 4 consecutive o (float4).
// ---------------------------------------------------------------------------
__global__ void __launch_bounds__(256)
epilogue(const float* __restrict__ bias, float* __restrict__ out)
{
    const int tid = threadIdx.x;
    const int n   = blockIdx.x * 8 + (tid >> 5);       // 8 n per block
    const int o4  = (tid & 31) * 4;                    // 4 o's per thread
    const float* S = g_S + (size_t)n * NJ2;

    float4 C0[2], C4[2], CR[3][2], CI[3][2];
    #pragma unroll
    for (int k = 0; k < 2; k++) {
        C0[k] = *(const float4*)&S[k * OO + o4];
        C4[k] = *(const float4*)&S[256 + k * OO + o4];
        #pragma unroll
        for (int om = 1; om <= 3; om++) {
            const int base = (2 + 3 * (om - 1)) * 256 + k * OO + o4;
            const float4 m1 = *(const float4*)&S[base];
            const float4 m2 = *(const float4*)&S[base + 256];
            const float4 m3 = *(const float4*)&S[base + 512];
            CR[om - 1][k] = make_float4(m1.x + m2.x, m1.y + m2.y, m1.z + m2.z, m1.w + m2.w);
            CI[om - 1][k] = make_float4(m1.x - m3.x, m1.y - m3.y, m1.z - m3.z, m1.w - m3.w);
        }
    }

    const float ct[8] = {1.f, 0.70710678f, 0.f, -0.70710678f,
                         -1.f, -0.70710678f, 0.f, 0.70710678f};
    const float st[8] = {0.f, 0.70710678f, 1.f, 0.70710678f,
                         0.f, -0.70710678f, -1.f, -0.70710678f};
    const float4 b0v = *(const float4*)&bias[o4];
    const float4 b1v = *(const float4*)&bias[OO + o4];

    #pragma unroll
    for (int rot = 0; rot < 8; rot++) {
        const float sgn = (rot & 1) ? -1.f : 1.f;
        float4 s0, s1;
        s0.x = C0[0].x + sgn * C4[0].x;  s0.y = C0[0].y + sgn * C4[0].y;
        s0.z = C0[0].z + sgn * C4[0].z;  s0.w = C0[0].w + sgn * C4[0].w;
        s1.x = C0[1].x + sgn * C4[1].x;  s1.y = C0[1].y + sgn * C4[1].y;
        s1.z = C0[1].z + sgn * C4[1].z;  s1.w = C0[1].w + sgn * C4[1].w;
        #pragma unroll
        for (int om = 1; om <= 3; om++) {
            const int ph = (om * rot) & 7;
            const float cc = ct[ph], ss = st[ph];
            s0.x += CR[om-1][0].x * cc - CI[om-1][0].x * ss;
            s0.y += CR[om-1][0].y * cc - CI[om-1][0].y * ss;
            s0.z += CR[om-1][0].z * cc - CI[om-1][0].z * ss;
            s0.w += CR[om-1][0].w * cc - CI[om-1][0].w * ss;
            s1.x += CR[om-1][1].x * cc - CI[om-1][1].x * ss;
            s1.y += CR[om-1][1].y * cc - CI[om-1][1].y * ss;
            s1.z += CR[om-1][1].z * cc - CI[om-1][1].z * ss;
            s1.w += CR[om-1][1].w * cc - CI[om-1][1].w * ss;
        }
        float4 r;
        r.x = fmaxf(s0.x + 40.f * b0v.x, 0.f) + fmaxf(s1.x + 40.f * b1v.x, 0.f);
        r.y = fmaxf(s0.y + 40.f * b0v.y, 0.f) + fmaxf(s1.y + 40.f * b1v.y, 0.f);
        r.z = fmaxf(s0.z + 40.f * b0v.z, 0.f) + fmaxf(s1.z + 40.f * b1v.z, 0.f);
        r.w = fmaxf(s0.w + 40.f * b0v.w, 0.f) + fmaxf(s1.w + 40.f * b1v.w, 0.f);
        *(float4*)&out[(size_t)n * (NROT * OO) + rot * OO + o4] = r;
    }
}

// ---------------------------------------------------------------------------
extern "C" void kernel_launch(void* const* d_in, const int* in_sizes, int n_in,
                              void* d_out, int out_size)
{
    const float *ms = nullptr, *bary = nullptr, *W = nullptr,
                *bias = nullptr, *interp = nullptr;
    for (int i = 0; i < n_in; i++) {
        switch (in_sizes[i]) {
            case NV * FF:             ms     = (const float*)d_in[i]; break;
            case NV * RA * 3 * 2:     bary   = (const float*)d_in[i]; break;
            case RA * KK * OO * FF:   W      = (const float*)d_in[i]; break;
            case KK * OO:             bias   = (const float*)d_in[i]; break;
            case RA * RA:             interp = (const float*)d_in[i]; break;
            default: break;
        }
    }
    float* out = (float*)d_out;

    prep<<<280, 128>>>(W, interp);
    gatherA<<<NV, 256>>>(ms, bary);

    cudaFuncSetAttribute(gemm_mma, cudaFuncAttributeMaxDynamicSharedMemorySize, DYNSMEM);
    dim3 gg(2 * NGRP, (NV + BM - 1) / BM);
    gemm_mma<<<gg, 256, DYNSMEM>>>();

    epilogue<<<NV / 8, 256>>>(bias, out);
}

// round 16
// speedup vs baseline: 1.0927x; 1.0264x over previous
#include <cuda_runtime.h>
#include <cuda_fp16.h>
#include <cstdint>

// ---------------- problem constants ----------------
#define NV    6000
#define RR    5
#define AA    8
#define FF    128
#define KK    2
#define OO    128
#define RA    40
#define NROT  8
#define NP    55                  // spectral p-rows incl. u (8 comps*5 + 3 u*5)
#define KDIMA 7040                // NP*128 A' columns
#define NGRP  11                  // column groups, each 256 cols, K=640
#define NJ2   (NGRP*256)          // 2816 spectral output cols
#define KG    640                 // uniform per-group K

// ---------------- GEMM tiling ----------------
#define BM    128
#define BN    128
#define BK    64
#define ASTB  144
#define A_BYTES (BM*ASTB)
#define B_BYTES (BN*ASTB)
#define STG_BYTES (A_BYTES + B_BYTES)
#define NSTG  3
#define DYNSMEM (NSTG*STG_BYTES)  // 110592 -> 2 CTAs/SM

// ---------------- scratch ----------------
__device__ __half g_A [(size_t)NV * KDIMA];    // spectral A' (+u cols)
__device__ __half g_B2[(size_t)NJ2 * KG];      // Karatsuba B
__device__ __half g_Sh[(size_t)NV * NJ2];      // spectral GEMM result (fp16)
__device__ __half g_Mh[64 * 48];               // padded fold matrix (fp16)

__device__ __constant__ int c_aoff[NGRP] =
    {0, 4480, 5120, 640, 1280, 5760, 1920, 2560, 6400, 3200, 3840};

// ---------------- PTX helpers ----------------
__device__ __forceinline__ uint32_t smem_u32(const void* p) {
    uint32_t a;
    asm("{ .reg .u64 t; cvta.to.shared.u64 t, %1; cvt.u32.u64 %0, t; }"
        : "=r"(a) : "l"(p));
    return a;
}
__device__ __forceinline__ void cpasync16(uint32_t saddr, const void* g, int srcsz) {
    asm volatile("cp.async.cg.shared.global [%0], [%1], 16, %2;"
                 :: "r"(saddr), "l"(g), "r"(srcsz) : "memory");
}
#define CP_COMMIT() asm volatile("cp.async.commit_group;" ::: "memory")
#define CP_WAIT1()  asm volatile("cp.async.wait_group 1;" ::: "memory")

__device__ __forceinline__ void ldsm_x4(uint32_t* r, uint32_t addr) {
    asm volatile("ldmatrix.sync.aligned.m8n8.x4.shared.b16 {%0,%1,%2,%3}, [%4];"
                 : "=r"(r[0]), "=r"(r[1]), "=r"(r[2]), "=r"(r[3]) : "r"(addr));
}
__device__ __forceinline__ void ldsm_x4_t(uint32_t* r, uint32_t addr) {
    asm volatile("ldmatrix.sync.aligned.m8n8.x4.trans.shared.b16 {%0,%1,%2,%3}, [%4];"
                 : "=r"(r[0]), "=r"(r[1]), "=r"(r[2]), "=r"(r[3]) : "r"(addr));
}
__device__ __forceinline__ void mma_f16(float* d, const uint32_t* a, const uint32_t* b) {
    asm volatile(
        "mma.sync.aligned.m16n8k16.row.col.f32.f16.f16.f32 "
        "{%0,%1,%2,%3}, {%4,%5,%6,%7}, {%8,%9}, {%0,%1,%2,%3};"
        : "+f"(d[0]), "+f"(d[1]), "+f"(d[2]), "+f"(d[3])
        : "r"(a[0]), "r"(a[1]), "r"(a[2]), "r"(a[3]), "r"(b[0]), "r"(b[1]));
}

// ---------------------------------------------------------------------------
// Kernel 1 (merged prep): blocks [0,256) buildB one-pass; [256,280) make_M.
// ---------------------------------------------------------------------------
__global__ void __launch_bounds__(128)
prep(const float* __restrict__ W, const float* __restrict__ interp)
{
    const int bid = blockIdx.x;
    const int tid = threadIdx.x;

    if (bid < 256) {
        const int k = bid >> 7;
        const int o = bid & 127;
        const int f = tid;
        const int ko = k * OO + o;

        float w[RR][AA];
        #pragma unroll
        for (int r = 0; r < RR; r++)
            #pragma unroll
            for (int b = 0; b < AA; b++)
                w[r][b] = __ldg(&W[((((size_t)(r * AA + b)) * KK + k) * OO + o) * FF + f]);

        #pragma unroll
        for (int r = 0; r < RR; r++) {
            float s0 = 0.f, s4 = 0.f;
            #pragma unroll
            for (int b = 0; b < AA; b++) {
                s0 += w[r][b];
                s4 += ((b & 1) ? -w[r][b] : w[r][b]);
            }
            g_B2[(size_t)(0 * 256 + ko) * KG + r * FF + f] = __float2half_rn(0.125f * s0);
            g_B2[(size_t)(1 * 256 + ko) * KG + r * FF + f] = __float2half_rn(0.125f * s4);
        }
        #pragma unroll
        for (int om = 1; om <= 3; om++) {
            const int base = 2 + 3 * (om - 1);
            #pragma unroll
            for (int r = 0; r < RR; r++) {
                float sr = 0.f, si = 0.f;
                #pragma unroll
                for (int b = 0; b < AA; b++) {
                    const float x = 0.25f * (float)(om * b);
                    sr = fmaf(cospif(x), w[r][b], sr);
                    si = fmaf(-sinpif(x), w[r][b], si);
                }
                const float whr = 0.25f * sr, whi = 0.25f * si;
                g_B2[(size_t)((base    ) * 256 + ko) * KG + r * FF + f] = __float2half_rn(whi);
                g_B2[(size_t)((base + 1) * 256 + ko) * KG + r * FF + f] = __float2half_rn(whr - whi);
                g_B2[(size_t)((base + 2) * 256 + ko) * KG + r * FF + f] = __float2half_rn(whr + whi);
            }
        }
    } else {
        const int e = (bid - 256) * 128 + tid;     // 0..3071
        const int p = e / 48, q = e % 48;
        float acc = 0.f;
        if (p < NP && q < RA) {
            const int r = p % RR;
            #pragma unroll
            for (int b = 0; b < AA; b++) {
                float coef;
                if (p < RA) {
                    const int comp = p / RR;
                    if (comp == 0)      coef = 1.f;
                    else if (comp == 7) coef = (b & 1) ? -1.f : 1.f;
                    else {
                        const int m = (comp + 1) >> 1;
                        const float x = 0.25f * (float)(m * b);
                        coef = (comp & 1) ? cospif(x) : -sinpif(x);
                    }
                } else {                       // u-rows: cos - sin
                    const int om = (p - RA) / RR + 1;
                    const float x = 0.25f * (float)(om * b);
                    coef = cospif(x) - sinpif(x);
                }
                acc += coef * interp[r * (AA * RA) + b * RA + q];
            }
        }
        g_Mh[p * 48 + q] = __float2half_rn(acc);
    }
}

// ---------------------------------------------------------------------------
// Kernel 2: gather (fp32) + barycentric -> smem; HMMA fold A' = M*sig.
// ---------------------------------------------------------------------------
__global__ void __launch_bounds__(256)
gatherA(const float* __restrict__ ms, const float* __restrict__ bary)
{
    __shared__ __half s_M  [64][56];
    __shared__ __half s_sig[48][136];
    __shared__ __half s_out[64][136];

    const int n    = blockIdx.x;
    const int tid  = threadIdx.x;
    const int wid  = tid >> 5;
    const int lane = tid & 31;

    for (int i = tid; i < 64 * 56; i += 256) {
        const int r = i / 56, c = i % 56;
        s_M[r][c] = (c < 48) ? g_Mh[r * 48 + c] : __float2half_rn(0.f);
    }
    for (int i = tid; i < 8 * 68; i += 256)
        *((uint32_t*)&s_sig[40 + i / 68][0] + (i % 68)) = 0u;

    #pragma unroll
    for (int it = 0; it < 5; it++) {
        const int q   = wid + 8 * it;
        const int row = n * RA + q;
        float bv = (lane < 6) ? bary[(size_t)row * 6 + lane] : 0.f;
        const int   i0 = (int)__shfl_sync(0xffffffffu, bv, 0);
        const float w0 =      __shfl_sync(0xffffffffu, bv, 1);
        const int   i1 = (int)__shfl_sync(0xffffffffu, bv, 2);
        const float w1 =      __shfl_sync(0xffffffffu, bv, 3);
        const int   i2 = (int)__shfl_sync(0xffffffffu, bv, 4);
        const float w2 =      __shfl_sync(0xffffffffu, bv, 5);

        const float4 a = __ldg((const float4*)(ms + (size_t)i0 * FF) + lane);
        const float4 b = __ldg((const float4*)(ms + (size_t)i1 * FF) + lane);
        const float4 c = __ldg((const float4*)(ms + (size_t)i2 * FF) + lane);
        const float v0 = w0 * a.x + w1 * b.x + w2 * c.x;
        const float v1 = w0 * a.y + w1 * b.y + w2 * c.y;
        const float v2 = w0 * a.z + w1 * b.z + w2 * c.z;
        const float v3 = w0 * a.w + w1 * b.w + w2 * c.w;
        *(__half2*)&s_sig[q][lane * 4]     = __floats2half2_rn(v0, v1);
        *(__half2*)&s_sig[q][lane * 4 + 2] = __floats2half2_rn(v2, v3);
    }
    __syncthreads();

    const uint32_t sMb = smem_u32(&s_M[0][0]);
    const uint32_t sSb = smem_u32(&s_sig[0][0]);
    const int grp = lane >> 3;
    const int wit = lane & 7;
    const int nc  = wid;

    uint32_t bfr[3][4];
    #pragma unroll
    for (int ks = 0; ks < 3; ks++)
        ldsm_x4_t(bfr[ks], sSb + (uint32_t)((ks * 16 + (grp & 1) * 8 + wit) * 272
                                            + (grp >> 1) * 16 + nc * 32));
    #pragma unroll
    for (int mt = 0; mt < 4; mt++) {
        float acc[2][4] = {{0.f,0.f,0.f,0.f},{0.f,0.f,0.f,0.f}};
        #pragma unroll
        for (int ks = 0; ks < 3; ks++) {
            uint32_t a[4];
            ldsm_x4(a, sMb + (uint32_t)((mt * 16 + (grp & 1) * 8 + wit) * 112
                                        + (grp >> 1) * 16 + ks * 32));
            mma_f16(acc[0], a, &bfr[ks][0]);
            mma_f16(acc[1], a, &bfr[ks][2]);
        }
        const int p  = mt * 16 + (lane >> 2);
        const int fb = nc * 16 + 2 * (lane & 3);
        *(__half2*)&s_out[p][fb]         = __floats2half2_rn(acc[0][0], acc[0][1]);
        *(__half2*)&s_out[p + 8][fb]     = __floats2half2_rn(acc[0][2], acc[0][3]);
        *(__half2*)&s_out[p][fb + 8]     = __floats2half2_rn(acc[1][0], acc[1][1]);
        *(__half2*)&s_out[p + 8][fb + 8] = __floats2half2_rn(acc[1][2], acc[1][3]);
    }
    __syncthreads();

    for (int i = tid; i < NP * 16; i += 256) {
        const int r = i >> 4, c = i & 15;
        uint4 v = *(const uint4*)&s_out[r][c * 8];
        *(uint4*)(g_A + (size_t)n * KDIMA + r * FF + c * 8) = v;
    }
}

// ---------------------------------------------------------------------------
// Kernel 3: uniform block-diagonal GEMM.  grid (22, 47), 2 CTAs/SM.
//   Stores S in fp16 (halves epilogue traffic).
// ---------------------------------------------------------------------------
__global__ void __launch_bounds__(256, 2)
gemm_mma()
{
    extern __shared__ char smem[];
    const uint32_t sbase = smem_u32(smem);

    const int tid = threadIdx.x;
    const int lid = tid & 31;
    const int wid = tid >> 5;
    const int wm  = wid >> 2;
    const int wn  = wid & 3;
    const int cg  = blockIdx.x;
    const int m0  = blockIdx.y * BM;
    const int gr  = cg >> 1;
    const int n0  = gr * 256 + (cg & 1) * 128;
    const int aoff = c_aoff[gr];
    const int ns   = KG / BK;            // 10

    const int grp = lid >> 3;
    const int wit = lid & 7;
    const uint32_t aoffs = (uint32_t)((wm * 64 + (grp & 1) * 8 + wit) * ASTB
                                      + (grp >> 1) * 16);
    const uint32_t boffs = (uint32_t)A_BYTES
                         + (uint32_t)((wn * 32 + (grp >> 1) * 8 + wit) * ASTB
                                      + (grp & 1) * 16);

    float acc[4][4][4];
    #pragma unroll
    for (int mt = 0; mt < 4; mt++)
        #pragma unroll
        for (int nt = 0; nt < 4; nt++)
            #pragma unroll
            for (int i = 0; i < 4; i++) acc[mt][nt][i] = 0.f;

    auto issue_stage = [&](int sp) {
        const int kk0 = sp * BK;
        const uint32_t sb = sbase + (uint32_t)(sp % NSTG) * STG_BYTES;
        #pragma unroll
        for (int i = 0; i < 4; i++) {
            const int id  = tid + i * 256;
            const int r   = id >> 3;
            const int c16 = id & 7;
            const int gm  = m0 + r;
            const bool v  = gm < NV;
            const __half* gp = g_A + (size_t)(v ? gm : 0) * KDIMA + aoff + kk0 + c16 * 8;
            cpasync16(sb + r * ASTB + c16 * 16, gp, v ? 16 : 0);
        }
        #pragma unroll
        for (int i = 0; i < 4; i++) {
            const int id  = tid + i * 256;
            const int r   = id >> 3;
            const int c16 = id & 7;
            const __half* gp = g_B2 + (size_t)(n0 + r) * KG + kk0 + c16 * 8;
            cpasync16(sb + A_BYTES + r * ASTB + c16 * 16, gp, 16);
        }
        CP_COMMIT();
    };

    issue_stage(0);
    issue_stage(1);

    for (int s = 0; s < ns; s++) {
        CP_WAIT1();
        __syncthreads();
        if (s + 2 < ns) issue_stage(s + 2); else CP_COMMIT();

        const uint32_t sb = sbase + (uint32_t)(s % NSTG) * STG_BYTES;
        #pragma unroll
        for (int ks = 0; ks < 4; ks++) {
            uint32_t a[4][4], b[2][4];
            #pragma unroll
            for (int mt = 0; mt < 4; mt++)
                ldsm_x4(a[mt], sb + aoffs + mt * (16 * ASTB) + ks * 32);
            #pragma unroll
            for (int np = 0; np < 2; np++)
                ldsm_x4(b[np], sb + boffs + np * (16 * ASTB) + ks * 32);
            #pragma unroll
            for (int mt = 0; mt < 4; mt++) {
                #pragma unroll
                for (int np = 0; np < 2; np++) {
                    mma_f16(acc[mt][2 * np],     a[mt], &b[np][0]);
                    mma_f16(acc[mt][2 * np + 1], a[mt], &b[np][2]);
                }
            }
        }
    }

    const int q4 = lid >> 2;
    const int r4 = lid & 3;
    #pragma unroll
    for (int mt = 0; mt < 4; mt++) {
        const int r  = wm * 64 + mt * 16 + q4;
        const int gm = m0 + r;
        #pragma unroll
        for (int nt = 0; nt < 4; nt++) {
            const int c = wn * 32 + nt * 8 + 2 * r4;
            if (gm < NV)
                *(__half2*)&g_Sh[(size_t)gm * NJ2 + n0 + c] =
                    __floats2half2_rn(acc[mt][nt][0], acc[mt][nt][1]);
            if (gm + 8 < NV)
                *(__half2*)&g_Sh[(size_t)(gm + 8) * NJ2 + n0 + c] =
                    __floats2half2_rn(acc[mt][nt][2], acc[mt][nt][3]);
        }
    }
}

// ---------------------------------------------------------------------------
// Kernel 4: Karatsuba combine + iFFT + bias + relu + k-sum (fp16 S input).
//   4 vertices/block (64 threads each), thread owns 2 consecutive o.
// ---------------------------------------------------------------------------
__global__ void __launch_bounds__(256)
epilogue(const float* __restrict__ bias, float* __restrict__ out)
{
    const int tid = threadIdx.x;
    const int n   = blockIdx.x * 4 + (tid >> 6);       // 4 n per block
    const int o2  = (tid & 63) * 2;                    // 2 o's per thread
    const __half* S = g_Sh + (size_t)n * NJ2;

    float2 C0[2], C4[2], CR[3][2], CI[3][2];
    #pragma unroll
    for (int k = 0; k < 2; k++) {
        C0[k] = __half22float2(*(const __half2*)&S[k * OO + o2]);
        C4[k] = __half22float2(*(const __half2*)&S[256 + k * OO + o2]);
        #pragma unroll
        for (int om = 1; om <= 3; om++) {
            const int base = (2 + 3 * (om - 1)) * 256 + k * OO + o2;
            const float2 m1 = __half22float2(*(const __half2*)&S[base]);
            const float2 m2 = __half22float2(*(const __half2*)&S[base + 256]);
            const float2 m3 = __half22float2(*(const __half2*)&S[base + 512]);
            CR[om - 1][k] = make_float2(m1.x + m2.x, m1.y + m2.y);
            CI[om - 1][k] = make_float2(m1.x - m3.x, m1.y - m3.y);
        }
    }

    const float ct[8] = {1.f, 0.70710678f, 0.f, -0.70710678f,
                         -1.f, -0.70710678f, 0.f, 0.70710678f};
    const float st[8] = {0.f, 0.70710678f, 1.f, 0.70710678f,
                         0.f, -0.70710678f, -1.f, -0.70710678f};
    const float b0x = 40.f * __ldg(&bias[o2]);
    const float b0y = 40.f * __ldg(&bias[o2 + 1]);
    const float b1x = 40.f * __ldg(&bias[OO + o2]);
    const float b1y = 40.f * __ldg(&bias[OO + o2 + 1]);

    #pragma unroll
    for (int rot = 0; rot < 8; rot++) {
        const float sgn = (rot & 1) ? -1.f : 1.f;
        float s0x = C0[0].x + sgn * C4[0].x, s0y = C0[0].y + sgn * C4[0].y;
        float s1x = C0[1].x + sgn * C4[1].x, s1y = C0[1].y + sgn * C4[1].y;
        #pragma unroll
        for (int om = 1; om <= 3; om++) {
            const int ph = (om * rot) & 7;
            const float cc = ct[ph], ss = st[ph];
            s0x += CR[om-1][0].x * cc - CI[om-1][0].x * ss;
            s0y += CR[om-1][0].y * cc - CI[om-1][0].y * ss;
            s1x += CR[om-1][1].x * cc - CI[om-1][1].x * ss;
            s1y += CR[om-1][1].y * cc - CI[om-1][1].y * ss;
        }
        float2 r;
        r.x = fmaxf(s0x + b0x, 0.f) + fmaxf(s1x + b1x, 0.f);
        r.y = fmaxf(s0y + b0y, 0.f) + fmaxf(s1y + b1y, 0.f);
        *(float2*)&out[(size_t)n * (NROT * OO) + rot * OO + o2] = r;
    }
}

// ---------------------------------------------------------------------------
extern "C" void kernel_launch(void* const* d_in, const int* in_sizes, int n_in,
                              void* d_out, int out_size)
{
    const float *ms = nullptr, *bary = nullptr, *W = nullptr,
                *bias = nullptr, *interp = nullptr;
    for (int i = 0; i < n_in; i++) {
        switch (in_sizes[i]) {
            case NV * FF:             ms     = (const float*)d_in[i]; break;
            case NV * RA * 3 * 2:     bary   = (const float*)d_in[i]; break;
            case RA * KK * OO * FF:   W      = (const float*)d_in[i]; break;
            case KK * OO:             bias   = (const float*)d_in[i]; break;
            case RA * RA:             interp = (const float*)d_in[i]; break;
            default: break;
        }
    }
    float* out = (float*)d_out;

    prep<<<280, 128>>>(W, interp);
    gatherA<<<NV, 256>>>(ms, bary);

    cudaFuncSetAttribute(gemm_mma, cudaFuncAttributeMaxDynamicSharedMemorySize, DYNSMEM);
    dim3 gg(2 * NGRP, (NV + BM - 1) / BM);
    gemm_mma<<<gg, 256, DYNSMEM>>>();

    epilogue<<<NV / 4, 256>>>(bias, out);
}

// round 17
// speedup vs baseline: 1.1573x; 1.0591x over previous
#include <cuda_runtime.h>
#include <cuda_fp16.h>
#include <cstdint>

// ---------------- problem constants ----------------
#define NV    6000
#define RR    5
#define AA    8
#define FF    128
#define KK    2
#define OO    128
#define RA    40
#define NROT  8
#define NP    55                  // spectral p-rows incl. u (8 comps*5 + 3 u*5)
#define KDIMA 7040                // NP*128 A' columns
#define NGRP  11                  // column groups, each 256 cols, K=640
#define NJ2   (NGRP*256)          // 2816 spectral output cols
#define KG    640                 // uniform per-group K

// ---------------- GEMM tiling ----------------
#define BM    128
#define BN    128
#define BK    64
#define ASTB  144
#define A_BYTES (BM*ASTB)
#define B_BYTES (BN*ASTB)
#define STG_BYTES (A_BYTES + B_BYTES)
#define NSTG  3
#define DYNSMEM (NSTG*STG_BYTES)  // 110592 -> 2 CTAs/SM

// ---------------- scratch ----------------
__device__ __half g_ms16[(size_t)NV * FF];     // fp16 mesh signal (1.5 MB)
__device__ __half g_A [(size_t)NV * KDIMA];    // spectral A' (+u cols)
__device__ __half g_B2[(size_t)NJ2 * KG];      // Karatsuba B
__device__ __half g_Sh[(size_t)NV * NJ2];      // spectral GEMM result (fp16)
__device__ __half g_Mh[64 * 48];               // padded fold matrix (fp16)

__device__ __constant__ int c_aoff[NGRP] =
    {0, 4480, 5120, 640, 1280, 5760, 1920, 2560, 6400, 3200, 3840};

// ---------------- PTX helpers ----------------
__device__ __forceinline__ uint32_t smem_u32(const void* p) {
    uint32_t a;
    asm("{ .reg .u64 t; cvta.to.shared.u64 t, %1; cvt.u32.u64 %0, t; }"
        : "=r"(a) : "l"(p));
    return a;
}
__device__ __forceinline__ void cpasync16(uint32_t saddr, const void* g, int srcsz) {
    asm volatile("cp.async.cg.shared.global [%0], [%1], 16, %2;"
                 :: "r"(saddr), "l"(g), "r"(srcsz) : "memory");
}
#define CP_COMMIT() asm volatile("cp.async.commit_group;" ::: "memory")
#define CP_WAIT1()  asm volatile("cp.async.wait_group 1;" ::: "memory")

__device__ __forceinline__ void ldsm_x4(uint32_t* r, uint32_t addr) {
    asm volatile("ldmatrix.sync.aligned.m8n8.x4.shared.b16 {%0,%1,%2,%3}, [%4];"
                 : "=r"(r[0]), "=r"(r[1]), "=r"(r[2]), "=r"(r[3]) : "r"(addr));
}
__device__ __forceinline__ void ldsm_x4_t(uint32_t* r, uint32_t addr) {
    asm volatile("ldmatrix.sync.aligned.m8n8.x4.trans.shared.b16 {%0,%1,%2,%3}, [%4];"
                 : "=r"(r[0]), "=r"(r[1]), "=r"(r[2]), "=r"(r[3]) : "r"(addr));
}
__device__ __forceinline__ void mma_f16(float* d, const uint32_t* a, const uint32_t* b) {
    asm volatile(
        "mma.sync.aligned.m16n8k16.row.col.f32.f16.f16.f32 "
        "{%0,%1,%2,%3}, {%4,%5,%6,%7}, {%8,%9}, {%0,%1,%2,%3};"
        : "+f"(d[0]), "+f"(d[1]), "+f"(d[2]), "+f"(d[3])
        : "r"(a[0]), "r"(a[1]), "r"(a[2]), "r"(a[3]), "r"(b[0]), "r"(b[1]));
}

// ---------------------------------------------------------------------------
// Kernel 1 (merged prep): [0,256) buildB; [256,280) make_M; [280,1030) conv_ms.
// ---------------------------------------------------------------------------
__global__ void __launch_bounds__(128)
prep(const float* __restrict__ ms, const float* __restrict__ W,
     const float* __restrict__ interp)
{
    const int bid = blockIdx.x;
    const int tid = threadIdx.x;

    if (bid < 256) {
        const int k = bid >> 7;
        const int o = bid & 127;
        const int f = tid;
        const int ko = k * OO + o;

        float w[RR][AA];
        #pragma unroll
        for (int r = 0; r < RR; r++)
            #pragma unroll
            for (int b = 0; b < AA; b++)
                w[r][b] = __ldg(&W[((((size_t)(r * AA + b)) * KK + k) * OO + o) * FF + f]);

        #pragma unroll
        for (int r = 0; r < RR; r++) {
            float s0 = 0.f, s4 = 0.f;
            #pragma unroll
            for (int b = 0; b < AA; b++) {
                s0 += w[r][b];
                s4 += ((b & 1) ? -w[r][b] : w[r][b]);
            }
            g_B2[(size_t)(0 * 256 + ko) * KG + r * FF + f] = __float2half_rn(0.125f * s0);
            g_B2[(size_t)(1 * 256 + ko) * KG + r * FF + f] = __float2half_rn(0.125f * s4);
        }
        #pragma unroll
        for (int om = 1; om <= 3; om++) {
            const int base = 2 + 3 * (om - 1);
            #pragma unroll
            for (int r = 0; r < RR; r++) {
                float sr = 0.f, si = 0.f;
                #pragma unroll
                for (int b = 0; b < AA; b++) {
                    const float x = 0.25f * (float)(om * b);
                    sr = fmaf(cospif(x), w[r][b], sr);
                    si = fmaf(-sinpif(x), w[r][b], si);
                }
                const float whr = 0.25f * sr, whi = 0.25f * si;
                g_B2[(size_t)((base    ) * 256 + ko) * KG + r * FF + f] = __float2half_rn(whi);
                g_B2[(size_t)((base + 1) * 256 + ko) * KG + r * FF + f] = __float2half_rn(whr - whi);
                g_B2[(size_t)((base + 2) * 256 + ko) * KG + r * FF + f] = __float2half_rn(whr + whi);
            }
        }
    } else if (bid < 280) {
        const int e = (bid - 256) * 128 + tid;     // 0..3071
        const int p = e / 48, q = e % 48;
        float acc = 0.f;
        if (p < NP && q < RA) {
            const int r = p % RR;
            #pragma unroll
            for (int b = 0; b < AA; b++) {
                float coef;
                if (p < RA) {
                    const int comp = p / RR;
                    if (comp == 0)      coef = 1.f;
                    else if (comp == 7) coef = (b & 1) ? -1.f : 1.f;
                    else {
                        const int m = (comp + 1) >> 1;
                        const float x = 0.25f * (float)(m * b);
                        coef = (comp & 1) ? cospif(x) : -sinpif(x);
                    }
                } else {                       // u-rows: cos - sin
                    const int om = (p - RA) / RR + 1;
                    const float x = 0.25f * (float)(om * b);
                    coef = cospif(x) - sinpif(x);
                }
                acc += coef * interp[r * (AA * RA) + b * RA + q];
            }
        }
        g_Mh[p * 48 + q] = __float2half_rn(acc);
    } else {
        // conv_ms: fp32 -> fp16 signal.  750 blocks x 128 thr x 4 half2.
        const int base = (bid - 280) * 512 + tid * 4;
        #pragma unroll
        for (int j = 0; j < 4; j++) {
            const int i = base + j;
            const float2 v = __ldg((const float2*)ms + i);
            *((__half2*)g_ms16 + i) = __floats2half2_rn(v.x, v.y);
        }
    }
}

// ---------------------------------------------------------------------------
// Kernel 2: gatherA — batched-MLP fp16 gather + barycentric + HMMA fold.
//   Phase 1: 5 bary loads (independent), shfl-extract.
//   Phase 2: all 15 fp16 gathers issued concurrently (MLP 15).
//   Phase 3: fp32 combine -> s_sig; HMMA fold; coalesced A' store.
// ---------------------------------------------------------------------------
__global__ void __launch_bounds__(256)
gatherA(const float* __restrict__ bary)
{
    __shared__ __half s_M  [64][56];
    __shared__ __half s_sig[48][136];
    __shared__ __half s_out[64][136];

    const int n    = blockIdx.x;
    const int tid  = threadIdx.x;
    const int wid  = tid >> 5;
    const int lane = tid & 31;

    for (int i = tid; i < 64 * 56; i += 256) {
        const int r = i / 56, c = i % 56;
        s_M[r][c] = (c < 48) ? g_Mh[r * 48 + c] : __float2half_rn(0.f);
    }
    for (int i = tid; i < 8 * 68; i += 256)
        *((uint32_t*)&s_sig[40 + i / 68][0] + (i % 68)) = 0u;

    // Phase 1: all bary loads first (independent), then extract.
    float bv[5];
    #pragma unroll
    for (int it = 0; it < 5; it++) {
        const int row = n * RA + wid + 8 * it;
        bv[it] = (lane < 6) ? __ldg(&bary[(size_t)row * 6 + lane]) : 0.f;
    }
    int   i0[5], i1[5], i2[5];
    float w0[5], w1[5], w2[5];
    #pragma unroll
    for (int it = 0; it < 5; it++) {
        i0[it] = (int)__shfl_sync(0xffffffffu, bv[it], 0);
        w0[it] =      __shfl_sync(0xffffffffu, bv[it], 1);
        i1[it] = (int)__shfl_sync(0xffffffffu, bv[it], 2);
        w1[it] =      __shfl_sync(0xffffffffu, bv[it], 3);
        i2[it] = (int)__shfl_sync(0xffffffffu, bv[it], 4);
        w2[it] =      __shfl_sync(0xffffffffu, bv[it], 5);
    }

    // Phase 2: all 15 gathers in flight (fp16 signal, uint2 per lane).
    uint2 ga[5], gb[5], gc[5];
    #pragma unroll
    for (int it = 0; it < 5; it++) {
        ga[it] = __ldg((const uint2*)(g_ms16 + (size_t)i0[it] * FF) + lane);
        gb[it] = __ldg((const uint2*)(g_ms16 + (size_t)i1[it] * FF) + lane);
        gc[it] = __ldg((const uint2*)(g_ms16 + (size_t)i2[it] * FF) + lane);
    }

    // Phase 3: combine + store to s_sig.
    #pragma unroll
    for (int it = 0; it < 5; it++) {
        const int q = wid + 8 * it;
        const float2 a01 = __half22float2(*(const __half2*)&ga[it].x);
        const float2 a23 = __half22float2(*(const __half2*)&ga[it].y);
        const float2 b01 = __half22float2(*(const __half2*)&gb[it].x);
        const float2 b23 = __half22float2(*(const __half2*)&gb[it].y);
        const float2 c01 = __half22float2(*(const __half2*)&gc[it].x);
        const float2 c23 = __half22float2(*(const __half2*)&gc[it].y);
        const float v0 = w0[it] * a01.x + w1[it] * b01.x + w2[it] * c01.x;
        const float v1 = w0[it] * a01.y + w1[it] * b01.y + w2[it] * c01.y;
        const float v2 = w0[it] * a23.x + w1[it] * b23.x + w2[it] * c23.x;
        const float v3 = w0[it] * a23.y + w1[it] * b23.y + w2[it] * c23.y;
        *(__half2*)&s_sig[q][lane * 4]     = __floats2half2_rn(v0, v1);
        *(__half2*)&s_sig[q][lane * 4 + 2] = __floats2half2_rn(v2, v3);
    }
    __syncthreads();

    const uint32_t sMb = smem_u32(&s_M[0][0]);
    const uint32_t sSb = smem_u32(&s_sig[0][0]);
    const int grp = lane >> 3;
    const int wit = lane & 7;
    const int nc  = wid;

    uint32_t bfr[3][4];
    #pragma unroll
    for (int ks = 0; ks < 3; ks++)
        ldsm_x4_t(bfr[ks], sSb + (uint32_t)((ks * 16 + (grp & 1) * 8 + wit) * 272
                                            + (grp >> 1) * 16 + nc * 32));
    #pragma unroll
    for (int mt = 0; mt < 4; mt++) {
        float acc[2][4] = {{0.f,0.f,0.f,0.f},{0.f,0.f,0.f,0.f}};
        #pragma unroll
        for (int ks = 0; ks < 3; ks++) {
            uint32_t a[4];
            ldsm_x4(a, sMb + (uint32_t)((mt * 16 + (grp & 1) * 8 + wit) * 112
                                        + (grp >> 1) * 16 + ks * 32));
            mma_f16(acc[0], a, &bfr[ks][0]);
            mma_f16(acc[1], a, &bfr[ks][2]);
        }
        const int p  = mt * 16 + (lane >> 2);
        const int fb = nc * 16 + 2 * (lane & 3);
        *(__half2*)&s_out[p][fb]         = __floats2half2_rn(acc[0][0], acc[0][1]);
        *(__half2*)&s_out[p + 8][fb]     = __floats2half2_rn(acc[0][2], acc[0][3]);
        *(__half2*)&s_out[p][fb + 8]     = __floats2half2_rn(acc[1][0], acc[1][1]);
        *(__half2*)&s_out[p + 8][fb + 8] = __floats2half2_rn(acc[1][2], acc[1][3]);
    }
    __syncthreads();

    for (int i = tid; i < NP * 16; i += 256) {
        const int r = i >> 4, c = i & 15;
        uint4 v = *(const uint4*)&s_out[r][c * 8];
        *(uint4*)(g_A + (size_t)n * KDIMA + r * FF + c * 8) = v;
    }
}

// ---------------------------------------------------------------------------
// Kernel 3: uniform block-diagonal GEMM.  grid (22, 47), 2 CTAs/SM.
//   Stores S in fp16.  (R16 known-good, unchanged.)
// ---------------------------------------------------------------------------
__global__ void __launch_bounds__(256, 2)
gemm_mma()
{
    extern __shared__ char smem[];
    const uint32_t sbase = smem_u32(smem);

    const int tid = threadIdx.x;
    const int lid = tid & 31;
    const int wid = tid >> 5;
    const int wm  = wid >> 2;
    const int wn  = wid & 3;
    const int cg  = blockIdx.x;
    const int m0  = blockIdx.y * BM;
    const int gr  = cg >> 1;
    const int n0  = gr * 256 + (cg & 1) * 128;
    const int aoff = c_aoff[gr];
    const int ns   = KG / BK;            // 10

    const int grp = lid >> 3;
    const int wit = lid & 7;
    const uint32_t aoffs = (uint32_t)((wm * 64 + (grp & 1) * 8 + wit) * ASTB
                                      + (grp >> 1) * 16);
    const uint32_t boffs = (uint32_t)A_BYTES
                         + (uint32_t)((wn * 32 + (grp >> 1) * 8 + wit) * ASTB
                                      + (grp & 1) * 16);

    float acc[4][4][4];
    #pragma unroll
    for (int mt = 0; mt < 4; mt++)
        #pragma unroll
        for (int nt = 0; nt < 4; nt++)
            #pragma unroll
            for (int i = 0; i < 4; i++) acc[mt][nt][i] = 0.f;

    auto issue_stage = [&](int sp) {
        const int kk0 = sp * BK;
        const uint32_t sb = sbase + (uint32_t)(sp % NSTG) * STG_BYTES;
        #pragma unroll
        for (int i = 0; i < 4; i++) {
            const int id  = tid + i * 256;
            const int r   = id >> 3;
            const int c16 = id & 7;
            const int gm  = m0 + r;
            const bool v  = gm < NV;
            const __half* gp = g_A + (size_t)(v ? gm : 0) * KDIMA + aoff + kk0 + c16 * 8;
            cpasync16(sb + r * ASTB + c16 * 16, gp, v ? 16 : 0);
        }
        #pragma unroll
        for (int i = 0; i < 4; i++) {
            const int id  = tid + i * 256;
            const int r   = id >> 3;
            const int c16 = id & 7;
            const __half* gp = g_B2 + (size_t)(n0 + r) * KG + kk0 + c16 * 8;
            cpasync16(sb + A_BYTES + r * ASTB + c16 * 16, gp, 16);
        }
        CP_COMMIT();
    };

    issue_stage(0);
    issue_stage(1);

    for (int s = 0; s < ns; s++) {
        CP_WAIT1();
        __syncthreads();
        if (s + 2 < ns) issue_stage(s + 2); else CP_COMMIT();

        const uint32_t sb = sbase + (uint32_t)(s % NSTG) * STG_BYTES;
        #pragma unroll
        for (int ks = 0; ks < 4; ks++) {
            uint32_t a[4][4], b[2][4];
            #pragma unroll
            for (int mt = 0; mt < 4; mt++)
                ldsm_x4(a[mt], sb + aoffs + mt * (16 * ASTB) + ks * 32);
            #pragma unroll
            for (int np = 0; np < 2; np++)
                ldsm_x4(b[np], sb + boffs + np * (16 * ASTB) + ks * 32);
            #pragma unroll
            for (int mt = 0; mt < 4; mt++) {
                #pragma unroll
                for (int np = 0; np < 2; np++) {
                    mma_f16(acc[mt][2 * np],     a[mt], &b[np][0]);
                    mma_f16(acc[mt][2 * np + 1], a[mt], &b[np][2]);
                }
            }
        }
    }

    const int q4 = lid >> 2;
    const int r4 = lid & 3;
    #pragma unroll
    for (int mt = 0; mt < 4; mt++) {
        const int r  = wm * 64 + mt * 16 + q4;
        const int gm = m0 + r;
        #pragma unroll
        for (int nt = 0; nt < 4; nt++) {
            const int c = wn * 32 + nt * 8 + 2 * r4;
            if (gm < NV)
                *(__half2*)&g_Sh[(size_t)gm * NJ2 + n0 + c] =
                    __floats2half2_rn(acc[mt][nt][0], acc[mt][nt][1]);
            if (gm + 8 < NV)
                *(__half2*)&g_Sh[(size_t)(gm + 8) * NJ2 + n0 + c] =
                    __floats2half2_rn(acc[mt][nt][2], acc[mt][nt][3]);
        }
    }
}

// ---------------------------------------------------------------------------
// Kernel 4: Karatsuba combine + iFFT + bias + relu + k-sum (fp16 S input).
//   (R16 known-good, unchanged.)
// ---------------------------------------------------------------------------
__global__ void __launch_bounds__(256)
epilogue(const float* __restrict__ bias, float* __restrict__ out)
{
    const int tid = threadIdx.x;
    const int n   = blockIdx.x * 4 + (tid >> 6);
    const int o2  = (tid & 63) * 2;
    const __half* S = g_Sh + (size_t)n * NJ2;

    float2 C0[2], C4[2], CR[3][2], CI[3][2];
    #pragma unroll
    for (int k = 0; k < 2; k++) {
        C0[k] = __half22float2(*(const __half2*)&S[k * OO + o2]);
        C4[k] = __half22float2(*(const __half2*)&S[256 + k * OO + o2]);
        #pragma unroll
        for (int om = 1; om <= 3; om++) {
            const int base = (2 + 3 * (om - 1)) * 256 + k * OO + o2;
            const float2 m1 = __half22float2(*(const __half2*)&S[base]);
            const float2 m2 = __half22float2(*(const __half2*)&S[base + 256]);
            const float2 m3 = __half22float2(*(const __half2*)&S[base + 512]);
            CR[om - 1][k] = make_float2(m1.x + m2.x, m1.y + m2.y);
            CI[om - 1][k] = make_float2(m1.x - m3.x, m1.y - m3.y);
        }
    }

    const float ct[8] = {1.f, 0.70710678f, 0.f, -0.70710678f,
                         -1.f, -0.70710678f, 0.f, 0.70710678f};
    const float st[8] = {0.f, 0.70710678f, 1.f, 0.70710678f,
                         0.f, -0.70710678f, -1.f, -0.70710678f};
    const float b0x = 40.f * __ldg(&bias[o2]);
    const float b0y = 40.f * __ldg(&bias[o2 + 1]);
    const float b1x = 40.f * __ldg(&bias[OO + o2]);
    const float b1y = 40.f * __ldg(&bias[OO + o2 + 1]);

    #pragma unroll
    for (int rot = 0; rot < 8; rot++) {
        const float sgn = (rot & 1) ? -1.f : 1.f;
        float s0x = C0[0].x + sgn * C4[0].x, s0y = C0[0].y + sgn * C4[0].y;
        float s1x = C0[1].x + sgn * C4[1].x, s1y = C0[1].y + sgn * C4[1].y;
        #pragma unroll
        for (int om = 1; om <= 3; om++) {
            const int ph = (om * rot) & 7;
            const float cc = ct[ph], ss = st[ph];
            s0x += CR[om-1][0].x * cc - CI[om-1][0].x * ss;
            s0y += CR[om-1][0].y * cc - CI[om-1][0].y * ss;
            s1x += CR[om-1][1].x * cc - CI[om-1][1].x * ss;
            s1y += CR[om-1][1].y * cc - CI[om-1][1].y * ss;
        }
        float2 r;
        r.x = fmaxf(s0x + b0x, 0.f) + fmaxf(s1x + b1x, 0.f);
        r.y = fmaxf(s0y + b0y, 0.f) + fmaxf(s1y + b1y, 0.f);
        *(float2*)&out[(size_t)n * (NROT * OO) + rot * OO + o2] = r;
    }
}

// ---------------------------------------------------------------------------
extern "C" void kernel_launch(void* const* d_in, const int* in_sizes, int n_in,
                              void* d_out, int out_size)
{
    const float *ms = nullptr, *bary = nullptr, *W = nullptr,
                *bias = nullptr, *interp = nullptr;
    for (int i = 0; i < n_in; i++) {
        switch (in_sizes[i]) {
            case NV * FF:             ms     = (const float*)d_in[i]; break;
            case NV * RA * 3 * 2:     bary   = (const float*)d_in[i]; break;
            case RA * KK * OO * FF:   W      = (const float*)d_in[i]; break;
            case KK * OO:             bias   = (const float*)d_in[i]; break;
            case RA * RA:             interp = (const float*)d_in[i]; break;
            default: break;
        }
    }
    float* out = (float*)d_out;

    prep<<<1030, 128>>>(ms, W, interp);
    gatherA<<<NV, 256>>>(bary);

    cudaFuncSetAttribute(gemm_mma, cudaFuncAttributeMaxDynamicSharedMemorySize, DYNSMEM);
    dim3 gg(2 * NGRP, (NV + BM - 1) / BM);
    gemm_mma<<<gg, 256, DYNSMEM>>>();

    epilogue<<<NV / 4, 256>>>(bias, out);
}